// round 5
// baseline (speedup 1.0000x reference)
#include <cuda_runtime.h>
#include <cstdint>
#include <climits>

// ---------------- problem constants (match reference exactly) ----------------
#define BB   4
#define NPTS 300000
#define NC   5
#define GXX  432
#define GYY  496
#define GZZ  1
#define NVOX (GXX * GYY * GZZ)          // 214272
#define MAXV 40000
#define MAXP 30
#define CAP  48                          // per-voxel index bucket capacity
#define CHUNK 1024
#define NB   ((NVOX + CHUNK - 1) / CHUNK)   // 210

#define FEATS_ELEMS ((size_t)BB * MAXV * MAXP * NC)   // 24,000,000 floats
#define COORD_ELEMS ((size_t)BB * MAXV * 4)           // 640,000 floats
#define F4_FEATS (24000000 / 4)          // 6,000,000 float4

#define I4_CNT   ((BB * NVOX) / 4)       // 214,272 int4
#define I4_AGG   ((BB * NB + 3) / 4)
#define I4_VL    ((BB * MAXV) / 4)       // 40,000 int4
#define FILL_TOTAL (I4_CNT + I4_AGG + I4_VL)

#define VALIDF (1 << 30)
#define ROWF   (MAXP * NC)               // 150 floats per feats row

// ---------------- static device scratch (16B-aligned for vector ops) ----------
__device__ int4 g_count4[(BB * NVOX) / 4];
__device__ int4 g_agg4  [I4_AGG];
__device__ int4 g_vlist4[I4_VL];         // row -> vid (or -1)
__device__ int  g_bucket[(size_t)BB * NVOX * CAP];

#define G_COUNT ((int*)g_count4)
#define G_AGG   ((int*)g_agg4)
#define G_VLIST ((int*)g_vlist4)

// ---------------- tiny init: counts=0, agg=0, vlist=-1 ------------------------
__global__ void k_fill() {
    int i = blockIdx.x * blockDim.x + threadIdx.x;
    if (i < I4_CNT) { g_count4[i] = make_int4(0, 0, 0, 0); return; }
    i -= I4_CNT;
    if (i < I4_AGG) { g_agg4[i] = make_int4(0, 0, 0, 0); return; }
    i -= I4_AGG;
    if (i < I4_VL)  { g_vlist4[i] = make_int4(-1, -1, -1, -1); }
}

// ---------------- pass 1: voxelize + bucket append, feats-zero in the shadow --
// The feats memset (96MB of float4 stores) is interleaved here: this kernel is
// atomic-latency bound, so the streaming stores ride in its idle issue slots.
__global__ void k_points(const float* __restrict__ pts, float4* __restrict__ feats4) {
    int tid = blockIdx.x * blockDim.x + threadIdx.x;
    int nthreads = gridDim.x * blockDim.x;

    // issue the point loads first (long-latency, scoreboarded)
    float x = 0.f, y = 0.f, z = 0.f;
    bool havept = tid < BB * NPTS;
    if (havept) {
        const float* p = pts + (size_t)tid * NC;
        x = __ldg(p + 0); y = __ldg(p + 1); z = __ldg(p + 2);
    }

    // zero the feats region while the loads are in flight
    const float4 z4 = make_float4(0.f, 0.f, 0.f, 0.f);
    for (int i = tid; i < F4_FEATS; i += nthreads) feats4[i] = z4;

    if (!havept) return;
    int b = tid / NPTS;
    int n = tid - b * NPTS;
    // identical float32 ops as reference: floor((p - lo) / vs)
    int ix = (int)floorf((x - 0.0f)   / 0.16f);
    int iy = (int)floorf((y + 39.68f) / 0.16f);
    int iz = (int)floorf((z + 3.0f)   / 4.0f);
    if (ix < 0 || ix >= GXX || iy < 0 || iy >= GYY || iz < 0 || iz >= GZZ) return;
    int vid = (iz * GYY + iy) * GXX + ix;
    int cell = b * NVOX + vid;
    int pos = atomicAdd(&G_COUNT[cell], 1);
    if (pos < CAP) g_bucket[(size_t)cell * CAP + pos] = n;
}

// ---------------- single-pass scan with decoupled lookback --------------------
// 840 blocks (256 thr) all fit in one wave on 148 SMs -> spin-wait is safe.
// Produces the compact row -> vid list directly.
__global__ void k_scan() {
    int blk = blockIdx.x;
    int b  = blk / NB;
    int cb = blk - b * NB;
    int t  = threadIdx.x;
    __shared__ int sh[256];

    const int* cnt = G_COUNT + b * NVOX;
    int base = cb * CHUNK + t * 4;
    int f0 = 0, f1 = 0, f2 = 0, f3 = 0;
    if (base + 0 < NVOX) f0 = (cnt[base + 0] > 0);
    if (base + 1 < NVOX) f1 = (cnt[base + 1] > 0);
    if (base + 2 < NVOX) f2 = (cnt[base + 2] > 0);
    if (base + 3 < NVOX) f3 = (cnt[base + 3] > 0);
    int s = f0 + f1 + f2 + f3;
    sh[t] = s;
    __syncthreads();
    #pragma unroll
    for (int off = 1; off < 256; off <<= 1) {   // Hillis–Steele inclusive
        int v = (t >= off) ? sh[t - off] : 0;
        __syncthreads();
        sh[t] += v;
        __syncthreads();
    }
    int excl  = sh[t] - s;
    int total = sh[255];

    // publish this chunk's aggregate ASAP
    if (t == 0) atomicExch(&G_AGG[blk], total | VALIDF);

    // lookback: sum all predecessor aggregates (within this batch)
    int partial = 0;
    for (int j = t; j < cb; j += 256) {
        int v;
        do { v = atomicAdd(&G_AGG[b * NB + j], 0); } while (!(v & VALIDF));
        partial += (v & (VALIDF - 1));
    }
    __syncthreads();
    sh[t] = partial;
    __syncthreads();
    #pragma unroll
    for (int off = 128; off > 0; off >>= 1) {
        if (t < off) sh[t] += sh[t + off];
        __syncthreads();
    }
    int r = sh[0] + excl;

    int* vl = G_VLIST + b * MAXV;
    if (f0) { if (r < MAXV) vl[r] = base + 0; r++; }
    if (f1) { if (r < MAXV) vl[r] = base + 1; r++; }
    if (f2) { if (r < MAXV) vl[r] = base + 2; r++; }
    if (f3) { if (r < MAXV) vl[r] = base + 3; r++; }
}

// ---------------- emit: lean warp-per-row --------------------------------------
// Feats padding is already zero (written by k_points). Only real points and the
// coords float4 are stored here: lane l (< m) writes point-rank-l's 5 floats,
// which are contiguous within the row -> coalesced. ~1.4 pts/row avg.
__global__ void k_emit(const float* __restrict__ pts, float* __restrict__ out) {
    int gw = (blockIdx.x * blockDim.x + threadIdx.x) >> 5;
    if (gw >= BB * MAXV) return;
    int lane = threadIdx.x & 31;

    int row = gw;
    int b = row / MAXV;
    int vid = __ldg(&G_VLIST[row]);
    float4* co = (float4*)(out + FEATS_ELEMS) + row;

    if (vid < 0) {
        if (lane == 0) *co = make_float4(-1.f, -1.f, -1.f, -1.f);
        return;
    }

    int cell = b * NVOX + vid;
    int cnt = __ldg(&G_COUNT[cell]);
    int m = cnt < CAP ? cnt : CAP;
    const int* bk = g_bucket + (size_t)cell * CAP;

    // my point index and its original-order rank (indices are distinct)
    int v0 = (lane < m) ? __ldg(bk + lane) : INT_MAX;
    int r0 = 0;
    if (m > 1) {
        if (m <= 32) {                      // common path (P(m>32) ~ 0)
            #pragma unroll 4
            for (int j = 0; j < m; j++) {
                int vj = __shfl_sync(0xffffffffu, v0, j);
                r0 += (vj < v0);
            }
        } else {
            int v1 = (lane + 32 < m) ? __ldg(bk + lane + 32) : INT_MAX;
            for (int j = 0; j < m; j++) {
                int vj = (j < 32) ? __shfl_sync(0xffffffffu, v0, j)
                                  : __shfl_sync(0xffffffffu, v1, j - 32);
                r0 += (vj < v0);
            }
            // lanes' v1 elements that land in the first MAXP ranks
            int rr1 = 0;
            if (lane + 32 < m) {
                for (int j = 0; j < m; j++) {
                    int vj = (j < 32) ? __shfl_sync(0xffffffffu, v0, j)
                                      : __shfl_sync(0xffffffffu, v1, j - 32);
                    rr1 += (vj < v1);
                }
                if (rr1 < MAXP) {
                    const float* p = pts + ((size_t)b * NPTS + v1) * NC;
                    float* fo = out + (size_t)row * ROWF + rr1 * NC;
                    fo[0] = (__ldg(p + 0) - 0.0f)   / 69.12f;
                    fo[1] = (__ldg(p + 1) + 39.68f) / 79.36f;
                    fo[2] = (__ldg(p + 2) + 3.0f)   / 4.0f;
                    fo[3] = __ldg(p + 3);
                    fo[4] = __ldg(p + 4);
                }
            }
        }
    }

    if (lane < m && r0 < MAXP) {
        const float* p = pts + ((size_t)b * NPTS + v0) * NC;
        float* fo = out + (size_t)row * ROWF + r0 * NC;
        fo[0] = (__ldg(p + 0) - 0.0f)   / 69.12f;
        fo[1] = (__ldg(p + 1) + 39.68f) / 79.36f;
        fo[2] = (__ldg(p + 2) + 3.0f)   / 4.0f;
        fo[3] = __ldg(p + 3);
        fo[4] = __ldg(p + 4);
    }

    if (lane == 0) {
        int iz  = vid / (GXX * GYY);
        int rem = vid - iz * (GXX * GYY);
        *co = make_float4((float)b, (float)iz, (float)(rem / GXX), (float)(rem % GXX));
    }
}

// ---------------- launch ------------------------------------------------------
extern "C" void kernel_launch(void* const* d_in, const int* in_sizes, int n_in,
                              void* d_out, int out_size) {
    const float* pts = (const float*)d_in[0];
    float* out = (float*)d_out;

    k_fill  <<<(FILL_TOTAL + 255) / 256, 256>>>();
    k_points<<<(BB * NPTS + 255) / 256, 256>>>(pts, (float4*)out);
    k_scan  <<<BB * NB, 256>>>();
    k_emit  <<<(BB * MAXV * 32 + 255) / 256, 256>>>(pts, out);
}

// round 6
// speedup vs baseline: 1.1306x; 1.1306x over previous
#include <cuda_runtime.h>
#include <cstdint>
#include <climits>

// ---------------- problem constants (match reference exactly) ----------------
#define BB   4
#define NPTS 300000
#define NC   5
#define GXX  432
#define GYY  496
#define GZZ  1
#define NVOX (GXX * GYY * GZZ)          // 214272
#define MAXV 40000
#define MAXP 30
#define CAP  48                          // per-voxel index bucket capacity
#define CHUNK 1024
#define NB   ((NVOX + CHUNK - 1) / CHUNK)   // 210

#define FEATS_ELEMS ((size_t)BB * MAXV * MAXP * NC)   // 24,000,000 floats
#define F4_FEATS (24000000 / 4)          // 6,000,000 float4
#define F4_COORD ((BB * MAXV * 4) / 4)   // 160,000 float4

#define I4_CNT   ((BB * NVOX) / 4)       // 214,272 int4
#define I4_AGG   ((BB * NB + 3) / 4)
#define FILL_TOTAL (I4_CNT + I4_AGG + F4_COORD)

#define VALIDF (1 << 30)
#define ROWF   (MAXP * NC)               // 150 floats per feats row

// ---------------- static device scratch (16B-aligned for vector ops) ----------
__device__ int4 g_count4[(BB * NVOX) / 4];
__device__ int4 g_agg4  [I4_AGG];
__device__ int  g_rank  [BB * NVOX];     // cell -> absolute rank among occupied
__device__ int  g_bucket[(size_t)BB * NVOX * CAP];

#define G_COUNT ((int*)g_count4)
#define G_AGG   ((int*)g_agg4)

// ---------------- init: counts=0, agg=0, coords=-1 -----------------------------
__global__ void k_fill(float4* __restrict__ out4) {
    int i = blockIdx.x * blockDim.x + threadIdx.x;
    if (i < I4_CNT) { g_count4[i] = make_int4(0, 0, 0, 0); return; }
    i -= I4_CNT;
    if (i < I4_AGG) { g_agg4[i] = make_int4(0, 0, 0, 0); return; }
    i -= I4_AGG;
    if (i < F4_COORD) {
        out4[F4_FEATS + i] = make_float4(-1.f, -1.f, -1.f, -1.f);
    }
}

// ---------------- pass 1: voxelize + bucket append + feats zero ----------------
__global__ void k_points(const float* __restrict__ pts, float4* __restrict__ feats4) {
    int tid = blockIdx.x * blockDim.x + threadIdx.x;
    int nthreads = gridDim.x * blockDim.x;

    // issue the point loads first (long-latency, scoreboarded)
    float x = 0.f, y = 0.f, z = 0.f;
    bool havept = tid < BB * NPTS;
    if (havept) {
        const float* p = pts + (size_t)tid * NC;
        x = __ldg(p + 0); y = __ldg(p + 1); z = __ldg(p + 2);
    }

    // zero the feats region (unavoidable 96MB of streaming stores)
    const float4 z4 = make_float4(0.f, 0.f, 0.f, 0.f);
    for (int i = tid; i < F4_FEATS; i += nthreads) feats4[i] = z4;

    if (!havept) return;
    int b = tid / NPTS;
    int n = tid - b * NPTS;
    // identical float32 ops as reference: floor((p - lo) / vs)
    int ix = (int)floorf((x - 0.0f)   / 0.16f);
    int iy = (int)floorf((y + 39.68f) / 0.16f);
    int iz = (int)floorf((z + 3.0f)   / 4.0f);
    if (ix < 0 || ix >= GXX || iy < 0 || iy >= GYY || iz < 0 || iz >= GZZ) return;
    int vid = (iz * GYY + iy) * GXX + ix;
    int cell = b * NVOX + vid;
    int pos = atomicAdd(&G_COUNT[cell], 1);
    if (pos < CAP) g_bucket[(size_t)cell * CAP + pos] = n;
}

// ---------------- single-pass scan with decoupled lookback --------------------
// 840 blocks (256 thr) all fit in one wave on 148 SMs -> spin-wait is safe.
// Writes per-cell rank AND the coords rows directly (coords = f(vid, rank)).
__global__ void k_scan(float* __restrict__ out) {
    int blk = blockIdx.x;
    int b  = blk / NB;
    int cb = blk - b * NB;
    int t  = threadIdx.x;
    __shared__ int sh[256];

    const int* cnt = G_COUNT + b * NVOX;
    int base = cb * CHUNK + t * 4;
    int f0 = 0, f1 = 0, f2 = 0, f3 = 0;
    if (base + 0 < NVOX) f0 = (cnt[base + 0] > 0);
    if (base + 1 < NVOX) f1 = (cnt[base + 1] > 0);
    if (base + 2 < NVOX) f2 = (cnt[base + 2] > 0);
    if (base + 3 < NVOX) f3 = (cnt[base + 3] > 0);
    int s = f0 + f1 + f2 + f3;
    sh[t] = s;
    __syncthreads();
    #pragma unroll
    for (int off = 1; off < 256; off <<= 1) {   // Hillis–Steele inclusive
        int v = (t >= off) ? sh[t - off] : 0;
        __syncthreads();
        sh[t] += v;
        __syncthreads();
    }
    int excl  = sh[t] - s;
    int total = sh[255];

    // publish this chunk's aggregate ASAP
    if (t == 0) atomicExch(&G_AGG[blk], total | VALIDF);

    // lookback: sum all predecessor aggregates (within this batch)
    int partial = 0;
    for (int j = t; j < cb; j += 256) {
        int v;
        do { v = atomicAdd(&G_AGG[b * NB + j], 0); } while (!(v & VALIDF));
        partial += (v & (VALIDF - 1));
    }
    __syncthreads();
    sh[t] = partial;
    __syncthreads();
    #pragma unroll
    for (int off = 128; off > 0; off >>= 1) {
        if (t < off) sh[t] += sh[t + off];
        __syncthreads();
    }
    int r = sh[0] + excl;

    float4* coords = (float4*)(out + FEATS_ELEMS);
    #pragma unroll
    for (int q = 0; q < 4; q++) {
        int f = (q == 0) ? f0 : (q == 1) ? f1 : (q == 2) ? f2 : f3;
        if (f) {
            int vid = base + q;
            g_rank[b * NVOX + vid] = r;
            if (r < MAXV) {
                int izc = vid / (GXX * GYY);
                int rem = vid - izc * (GXX * GYY);
                coords[b * MAXV + r] = make_float4((float)b, (float)izc,
                                                   (float)(rem / GXX),
                                                   (float)(rem % GXX));
            }
            r++;
        }
    }
}

// ---------------- scatter: one thread per point --------------------------------
// Recomputes vid, looks up rank, derives original-order within-voxel rank by
// scanning the (tiny, L2-resident) bucket, writes this point's 5 floats.
__global__ void k_scatter(const float* __restrict__ pts, float* __restrict__ out) {
    int tid = blockIdx.x * blockDim.x + threadIdx.x;
    if (tid >= BB * NPTS) return;
    int b = tid / NPTS;
    int n = tid - b * NPTS;
    const float* p = pts + (size_t)tid * NC;
    float x = __ldg(p + 0), y = __ldg(p + 1), z = __ldg(p + 2);
    int ix = (int)floorf((x - 0.0f)   / 0.16f);
    int iy = (int)floorf((y + 39.68f) / 0.16f);
    int iz = (int)floorf((z + 3.0f)   / 4.0f);
    if (ix < 0 || ix >= GXX || iy < 0 || iy >= GYY || iz < 0 || iz >= GZZ) return;
    int vid = (iz * GYY + iy) * GXX + ix;
    int cell = b * NVOX + vid;

    int rank = __ldg(&g_rank[cell]);          // valid: this voxel is occupied
    if (rank >= MAXV) return;
    int cnt = __ldg(&G_COUNT[cell]);
    int m = cnt < CAP ? cnt : CAP;
    const int* bk = g_bucket + (size_t)cell * CAP;

    int r = 0;
    bool found = false;
    for (int j = 0; j < m; j++) {
        int e = __ldg(bk + j);
        r += (e < n);
        found |= (e == n);
    }
    if (!found || r >= MAXP) return;          // overflow-dropped or beyond 30

    float* fo = out + ((size_t)(b * MAXV + rank)) * ROWF + r * NC;
    fo[0] = (x - 0.0f)   / 69.12f;
    fo[1] = (y + 39.68f) / 79.36f;
    fo[2] = (z + 3.0f)   / 4.0f;
    fo[3] = __ldg(p + 3);
    fo[4] = __ldg(p + 4);
}

// ---------------- launch ------------------------------------------------------
extern "C" void kernel_launch(void* const* d_in, const int* in_sizes, int n_in,
                              void* d_out, int out_size) {
    const float* pts = (const float*)d_in[0];
    float* out = (float*)d_out;

    k_fill   <<<(FILL_TOTAL + 255) / 256, 256>>>((float4*)out);
    k_points <<<(BB * NPTS + 255) / 256, 256>>>(pts, (float4*)out);
    k_scan   <<<BB * NB, 256>>>(out);
    k_scatter<<<(BB * NPTS + 255) / 256, 256>>>(pts, out);
}